// round 2
// baseline (speedup 1.0000x reference)
#include <cuda_runtime.h>
#include <math.h>

// Problem constants
#define NN 9216      // H*W = 96*96
#define CC 64        // channels
#define C8 8         // C/8
#define BB 2         // batch

// -------- scratch (static device globals: no runtime allocation) ----------
__device__ float d_invsig[3];                       // 1/sigma for Wq, Wk, Wv
__device__ float d_f[BB * NN * C8];                 // keys   f[b][i][c8]
__device__ float d_g[BB * NN * C8];                 // queries g[b][j][c8]
__device__ float d_h[BB * NN * CC];                 // values h[b][i][c]

// ===========================================================================
// K1: spectral norm via power iteration on G = W W^T  (8x8 or 64x64).
// sigma = sqrt(lambda_max(G)).  3 blocks (one per matrix), 64 threads.
// ===========================================================================
__global__ void spec_kernel(const float* __restrict__ Wq,
                            const float* __restrict__ Wk,
                            const float* __restrict__ Wv) {
    __shared__ float Wsh[64 * 64];
    __shared__ float G[64 * 64];
    __shared__ float v[64];
    __shared__ float w[64];
    __shared__ float nrm;

    int mat = blockIdx.x;
    const float* W = (mat == 0) ? Wq : (mat == 1) ? Wk : Wv;
    int dim = (mat == 2) ? 64 : 8;
    int t = threadIdx.x;

    for (int i = t; i < dim * 64; i += 64) Wsh[i] = W[i];
    __syncthreads();

    if (t < dim) {
        for (int j = 0; j < dim; j++) {
            float s = 0.f;
            for (int c = 0; c < 64; c++) s += Wsh[t * 64 + c] * Wsh[j * 64 + c];
            G[t * 64 + j] = s;
        }
        v[t] = 1.f;
    }
    __syncthreads();

    for (int it = 0; it < 250; it++) {
        if (t < dim) {
            float s = 0.f;
            for (int j = 0; j < dim; j++) s += G[t * 64 + j] * v[j];
            w[t] = s;
        }
        __syncthreads();
        if (t == 0) {
            float s = 0.f;
            for (int j = 0; j < dim; j++) s += w[j] * w[j];
            nrm = sqrtf(s);                 // ||G v|| -> lambda_max estimate
        }
        __syncthreads();
        if (t < dim) v[t] = w[t] / nrm;
        __syncthreads();
    }
    if (t == 0) d_invsig[mat] = 1.f / sqrtf(nrm);   // 1/sigma
}

// ===========================================================================
// K2: f = Wq_n x + bq, g = Wk_n x + bk, h = Wv_n x + bv
// One thread per (b, n) column. Key-major outputs.
// Grid: 72 blocks x 256 threads.
// ===========================================================================
__global__ void __launch_bounds__(256) fgh_kernel(
        const float* __restrict__ x,
        const float* __restrict__ Wq, const float* __restrict__ bq,
        const float* __restrict__ Wk, const float* __restrict__ bk,
        const float* __restrict__ Wv, const float* __restrict__ bv) {
    __shared__ float wq[512];
    __shared__ float wk[512];
    __shared__ float wv[4096];
    __shared__ float sb[80];        // bq[0:8], bk[8:16], bv[16:80]

    int t = threadIdx.x;
    float iq = d_invsig[0], ik = d_invsig[1], iv = d_invsig[2];
    for (int i = t; i < 512; i += 256) { wq[i] = Wq[i] * iq; wk[i] = Wk[i] * ik; }
    for (int i = t; i < 4096; i += 256) wv[i] = Wv[i] * iv;
    if (t < 8)  { sb[t] = bq[t]; sb[8 + t] = bk[t]; }
    if (t < 64) sb[16 + t] = bv[t];
    __syncthreads();

    int gid = blockIdx.x * 256 + t;          // 0 .. 18431
    int b = gid / NN, n = gid % NN;

    float fa[8], ga[8], ha[64];
#pragma unroll
    for (int o = 0; o < 8; o++) { fa[o] = sb[o]; ga[o] = sb[8 + o]; }
#pragma unroll
    for (int o = 0; o < 64; o++) ha[o] = sb[16 + o];

    const float* xp = x + (size_t)b * CC * NN + n;
    for (int c = 0; c < 64; c++) {
        float xc = xp[(size_t)c * NN];
#pragma unroll
        for (int o = 0; o < 8; o++) {
            fa[o] += wq[o * 64 + c] * xc;
            ga[o] += wk[o * 64 + c] * xc;
        }
#pragma unroll
        for (int o = 0; o < 64; o++) ha[o] += wv[o * 64 + c] * xc;
    }

    size_t base8 = ((size_t)b * NN + n) * 8;
#pragma unroll
    for (int o = 0; o < 8; o++) { d_f[base8 + o] = fa[o]; d_g[base8 + o] = ga[o]; }
    size_t base64 = ((size_t)b * NN + n) * 64;
#pragma unroll
    for (int o = 0; o < 64; o++) d_h[base64 + o] = ha[o];
}

// ===========================================================================
// K3: two-pass tiled attention.
//   Block = (batch b, query tile of 64 columns j). Full C=64 rows in regs.
//   Pass 1: exact max m_j over all keys (score-only sweep, cheap: 8 FMA/pair).
//   Pass 2: P = exp(S - m), O += H @ P, l += colsum(P) per 64-key tile.
//   Epilogue: out = gamma * O / l + x.
// Thread layout: 256 = 16(ty: c) x 16(tx: q); each thread owns a 4x4 O tile.
// ===========================================================================
__global__ void __launch_bounds__(256) attn_kernel(
        const float* __restrict__ x,
        const float* __restrict__ gamma,
        float* __restrict__ out) {
    __shared__ __align__(16) float h_sh[64 * 64];   // [k][c]
    __shared__ __align__(16) float p_sh[64 * 68];   // [k][q], padded
    __shared__ float f_sh[64 * 9];                  // [k][d], padded
    __shared__ float g_sh[64 * 9];                  // [q][d], padded
    __shared__ float red[16 * 64];
    __shared__ float m_sh[64];
    __shared__ float l_sh[64];

    int t  = threadIdx.x;
    int tx = t & 15;        // query group
    int ty = t >> 4;        // channel / key group
    int b  = blockIdx.y;
    int qt = blockIdx.x;

    // stage g tile once
    const float* gp = d_g + ((size_t)b * NN + qt * 64) * 8;
    for (int i = t; i < 512; i += 256) g_sh[(i >> 3) * 9 + (i & 7)] = gp[i];
    __syncthreads();

    // this thread's 4 query vectors in registers
    float gq[4][8];
#pragma unroll
    for (int qq = 0; qq < 4; qq++)
#pragma unroll
        for (int d = 0; d < 8; d++) gq[qq][d] = g_sh[(tx * 4 + qq) * 9 + d];

    // ---------------- pass 1: exact max over keys ----------------
    float mloc[4] = {-1e30f, -1e30f, -1e30f, -1e30f};
    for (int kt = 0; kt < NN / 64; kt++) {
        const float* fp = d_f + ((size_t)b * NN + kt * 64) * 8;
        for (int i = t; i < 512; i += 256) f_sh[(i >> 3) * 9 + (i & 7)] = fp[i];
        __syncthreads();
#pragma unroll
        for (int kk = 0; kk < 4; kk++) {
            int k = ty * 4 + kk;
            float fk[8];
#pragma unroll
            for (int d = 0; d < 8; d++) fk[d] = f_sh[k * 9 + d];
#pragma unroll
            for (int qq = 0; qq < 4; qq++) {
                float s = 0.f;
#pragma unroll
                for (int d = 0; d < 8; d++) s += fk[d] * gq[qq][d];
                mloc[qq] = fmaxf(mloc[qq], s);
            }
        }
        __syncthreads();
    }
#pragma unroll
    for (int qq = 0; qq < 4; qq++) red[ty * 64 + tx * 4 + qq] = mloc[qq];
    __syncthreads();
    if (t < 64) {
        float mm = -1e30f;
        for (int r = 0; r < 16; r++) mm = fmaxf(mm, red[r * 64 + t]);
        m_sh[t] = mm;
    }
    __syncthreads();
    float mq[4];
#pragma unroll
    for (int qq = 0; qq < 4; qq++) mq[qq] = m_sh[tx * 4 + qq];

    // ---------------- pass 2: exp + PV GEMM + denominator ----------------
    float acc[4][4];
#pragma unroll
    for (int i = 0; i < 4; i++)
#pragma unroll
        for (int j = 0; j < 4; j++) acc[i][j] = 0.f;
    float lloc[4] = {0.f, 0.f, 0.f, 0.f};

    for (int kt = 0; kt < NN / 64; kt++) {
        const float* fp = d_f + ((size_t)b * NN + kt * 64) * 8;
        const float* hp = d_h + ((size_t)b * NN + kt * 64) * 64;
        for (int i = t; i < 512; i += 256) f_sh[(i >> 3) * 9 + (i & 7)] = fp[i];
        for (int i = t; i < 1024; i += 256)
            ((float4*)h_sh)[i] = ((const float4*)hp)[i];
        __syncthreads();

        // scores + exp -> p_sh, partial l
#pragma unroll
        for (int kk = 0; kk < 4; kk++) {
            int k = ty * 4 + kk;
            float fk[8];
#pragma unroll
            for (int d = 0; d < 8; d++) fk[d] = f_sh[k * 9 + d];
#pragma unroll
            for (int qq = 0; qq < 4; qq++) {
                float s = 0.f;
#pragma unroll
                for (int d = 0; d < 8; d++) s += fk[d] * gq[qq][d];
                float p = __expf(s - mq[qq]);
                lloc[qq] += p;
                p_sh[k * 68 + tx * 4 + qq] = p;
            }
        }
        __syncthreads();

        // O[64x64] += H[64x64]^T-view @ P[64x64]  (k contraction)
#pragma unroll 4
        for (int k = 0; k < 64; k++) {
            float4 hv = *(const float4*)(h_sh + k * 64 + ty * 4);
            float4 pv = *(const float4*)(p_sh + k * 68 + tx * 4);
            acc[0][0] += hv.x * pv.x; acc[0][1] += hv.x * pv.y;
            acc[0][2] += hv.x * pv.z; acc[0][3] += hv.x * pv.w;
            acc[1][0] += hv.y * pv.x; acc[1][1] += hv.y * pv.y;
            acc[1][2] += hv.y * pv.z; acc[1][3] += hv.y * pv.w;
            acc[2][0] += hv.z * pv.x; acc[2][1] += hv.z * pv.y;
            acc[2][2] += hv.z * pv.z; acc[2][3] += hv.z * pv.w;
            acc[3][0] += hv.w * pv.x; acc[3][1] += hv.w * pv.y;
            acc[3][2] += hv.w * pv.z; acc[3][3] += hv.w * pv.w;
        }
        __syncthreads();
    }

    // reduce denominator l across ty groups
#pragma unroll
    for (int qq = 0; qq < 4; qq++) red[ty * 64 + tx * 4 + qq] = lloc[qq];
    __syncthreads();
    if (t < 64) {
        float s = 0.f;
        for (int r = 0; r < 16; r++) s += red[r * 64 + t];
        l_sh[t] = s;
    }
    __syncthreads();

    float gam = gamma[0];
    float linv[4];
#pragma unroll
    for (int qq = 0; qq < 4; qq++) linv[qq] = 1.f / l_sh[tx * 4 + qq];

#pragma unroll
    for (int ccg = 0; ccg < 4; ccg++) {
        int c = ty * 4 + ccg;
        size_t base = ((size_t)b * CC + c) * NN + qt * 64 + tx * 4;
        float4 xin = *(const float4*)(x + base);
        float4 r;
        r.x = gam * acc[ccg][0] * linv[0] + xin.x;
        r.y = gam * acc[ccg][1] * linv[1] + xin.y;
        r.z = gam * acc[ccg][2] * linv[2] + xin.z;
        r.w = gam * acc[ccg][3] * linv[3] + xin.w;
        *(float4*)(out + base) = r;
    }
}

// ===========================================================================
extern "C" void kernel_launch(void* const* d_in, const int* in_sizes, int n_in,
                              void* d_out, int out_size) {
    const float* x     = (const float*)d_in[0];
    const float* Wq    = (const float*)d_in[1];
    const float* bq    = (const float*)d_in[2];
    const float* Wk    = (const float*)d_in[3];
    const float* bk    = (const float*)d_in[4];
    const float* Wv    = (const float*)d_in[5];
    const float* bv    = (const float*)d_in[6];
    const float* gamma = (const float*)d_in[7];
    float* out = (float*)d_out;

    spec_kernel<<<3, 64>>>(Wq, Wk, Wv);
    fgh_kernel<<<(BB * NN) / 256, 256>>>(x, Wq, bq, Wk, bk, Wv, bv);
    attn_kernel<<<dim3(NN / 64, BB), 256>>>(x, gamma, out);
}